// round 11
// baseline (speedup 1.0000x reference)
#include <cuda_runtime.h>
#include <cuda_fp16.h>
#include <cstdint>

// out[65536,64] = xa[65536,256]@wa[256,64] + xb[65536,256]@wb[256,64]
// fp16 two-term: A split (xh+xl, fp16), B single fp16.
// mma.sync.m16n8k16.f32.f16.f16.f32. rel_err ~2e-4 (proven numerics).
// CTA: 512 threads (16 warps x 32 rows = 512 rows), grid 128.
// B: one 64 KB fragment image per CTA, amortized over 16 warps.
// A: per-warp-private 2-stage cp.async ring (32 rows x 32 k fp32, 160B rows,
//    seg-XOR swizzle -> conflict-free LDS.64 reads). No CTA barriers in loop.

#define THREADS 512
#define M_TILE  512
#define NCHUNK  16                  // chunks of 32 k
#define SROWB   160                 // stage row stride (bytes)
#define STAGEB  (32 * SROWB)        // 5120 B per stage
#define WST     (2 * STAGEB)        // 10240 B per warp (2 stages)
#define B_OFF   (16 * WST)          // 163840
#define SMEM_BYTES (B_OFF + 65536)  // 229376 (<= 227 KB opt-in)

// fragment-packed B: index (t*8+ni)*32+L -> uint2 {b0,b1}, t = k-step 0..31
//   b0 = wh{k0,k0+1}, b1 = wh{k0+8,k0+9}; k0 = t*16+(L&3)*2, n = ni*8+(L>>2)
__device__ __align__(16) uint2 g_wfrag[32 * 8 * 32];   // 64 KB

__device__ __forceinline__ uint32_t h2pack(float lo, float hi) {
    uint32_t r;
    asm("cvt.rn.f16x2.f32 %0, %1, %2;" : "=r"(r) : "f"(hi), "f"(lo));
    return r;
}

__device__ __forceinline__ void h2unpack(uint32_t p, float& lo, float& hi) {
    asm("{ .reg .b16 l, h; mov.b32 {l, h}, %2;\n\t"
        "cvt.f32.f16 %0, l; cvt.f32.f16 %1, h; }"
        : "=f"(lo), "=f"(hi) : "r"(p));
}

__device__ __forceinline__ void split2h(float x0, float x1,
                                        uint32_t& hp, uint32_t& lp) {
    hp = h2pack(x0, x1);
    float h0, h1;
    h2unpack(hp, h0, h1);
    lp = h2pack(x0 - h0, x1 - h1);
}

__device__ __forceinline__ void mma16816(float* c, const uint32_t* a,
                                         uint32_t b0, uint32_t b1) {
    asm volatile(
        "mma.sync.aligned.m16n8k16.row.col.f32.f16.f16.f32 "
        "{%0,%1,%2,%3}, {%4,%5,%6,%7}, {%8,%9}, {%0,%1,%2,%3};"
        : "+f"(c[0]), "+f"(c[1]), "+f"(c[2]), "+f"(c[3])
        : "r"(a[0]), "r"(a[1]), "r"(a[2]), "r"(a[3]), "r"(b0), "r"(b1));
}

__device__ __forceinline__ uint32_t smem_u32(const void* p) {
    uint32_t a;
    asm("{ .reg .u64 t; cvta.to.shared.u64 t, %1; cvt.u32.u64 %0, t; }"
        : "=r"(a) : "l"(p));
    return a;
}

// stage swizzle: f(r) = 2*((r>>2)&3) + (r&1); addr of float word w in row r
__device__ __forceinline__ uint32_t stoff(int r, int w) {
    uint32_t f = 2u * (((uint32_t)r >> 2) & 3u) + ((uint32_t)r & 1u);
    return (uint32_t)(r * SROWB) + (((((uint32_t)w >> 2) ^ f) & 7u) << 4) +
           (((uint32_t)w & 3u) << 2);
}

// ---- pre-kernel: pack fp16(w) into fragment order (proven) ----
__global__ void wconv_kernel(const float* __restrict__ wa,
                             const float* __restrict__ wb) {
    int id = blockIdx.x * 256 + threadIdx.x;   // 0..8191
    int L  = id & 31;
    int ni = (id >> 5) & 7;
    int t  = id >> 8;                          // k-step 0..31
    int k0 = t * 16 + (L & 3) * 2;             // global k
    int n  = ni * 8 + (L >> 2);
    const float* __restrict__ w = (k0 < 256) ? wa : wb;
    int kk = k0 & 255;
    float v0 = w[kk * 64 + n];
    float v1 = w[(kk + 1) * 64 + n];
    float v8 = w[(kk + 8) * 64 + n];
    float v9 = w[(kk + 9) * 64 + n];
    g_wfrag[id] = make_uint2(h2pack(v0, v1), h2pack(v8, v9));
}

// ---- main kernel ----
__global__ void __launch_bounds__(THREADS, 1)
sshe_mma_kernel(const float* __restrict__ xa, const float* __restrict__ xb,
                float* __restrict__ out) {
    extern __shared__ uint8_t smem[];          // [16 warp rings][B image]
    uint2* sB = (uint2*)(smem + B_OFF);
    const uint32_t sbase = smem_u32(smem);
    const int tid = threadIdx.x;
    const int L = tid & 31;
    const int wid = tid >> 5;
    const long long row0 = (long long)blockIdx.x * M_TILE;

    // cp.async coords: lane L owns stage row L (128 B data = 8 x 16B segs)
    const uint32_t fL = 2u * (((uint32_t)L >> 2) & 3u) + ((uint32_t)L & 1u);
    const uint32_t wbase = sbase + (uint32_t)(wid * WST);
    const size_t growL = (size_t)(row0 + wid * 32 + L) * 256;

    auto issue_chunk = [&](int c, int s) {
        const float* __restrict__ xsrc = (c < 8) ? xa : xb;
        const float* g = xsrc + growL + (c & 7) * 32;
        const uint32_t d = wbase + (uint32_t)(s * STAGEB + L * SROWB);
#pragma unroll
        for (int i = 0; i < 8; i++) {
            asm volatile("cp.async.cg.shared.global [%0], [%1], 16;"
                         :: "r"(d + ((((uint32_t)i ^ fL) & 7u) << 4)),
                            "l"(g + i * 4) : "memory");
        }
        asm volatile("cp.async.commit_group;" ::: "memory");
    };

    // precomputed fragment read offsets (mi=0 block; mi=1 adds 16*SROWB)
    const int r0 = L >> 2;
    const int r1 = r0 + 8;
    const int w0 = (L & 3) * 2;
    uint32_t off[2][4];
#pragma unroll
    for (int ks = 0; ks < 2; ks++) {
        off[ks][0] = stoff(r0, ks * 16 + w0);
        off[ks][1] = stoff(r1, ks * 16 + w0);
        off[ks][2] = stoff(r0, ks * 16 + w0 + 8);
        off[ks][3] = stoff(r1, ks * 16 + w0 + 8);
    }

    float acc[2][8][4];
#pragma unroll
    for (int m = 0; m < 2; m++)
#pragma unroll
        for (int i = 0; i < 8; i++)
#pragma unroll
            for (int j = 0; j < 4; j++) acc[m][i][j] = 0.f;

    // prologue: chunk 0 in flight, copy B image, one CTA barrier
    issue_chunk(0, 0);
    {
        const uint4* src = (const uint4*)g_wfrag;
        uint4* dst = (uint4*)sB;
#pragma unroll
        for (int i = 0; i < 8; i++) dst[tid + i * THREADS] = src[tid + i * THREADS];
    }
    __syncthreads();   // B visible CTA-wide (only CTA barrier)

    for (int c = 0; c < NCHUNK; c++) {
        const int s = c & 1;
        if (c + 1 < NCHUNK) {
            issue_chunk(c + 1, s ^ 1);
            asm volatile("cp.async.wait_group 1;" ::: "memory");
        } else {
            asm volatile("cp.async.wait_group 0;" ::: "memory");
        }
        __syncwarp();   // all lanes' chunk-c data in this warp's stage

        const uint8_t* st = smem + wid * WST + s * STAGEB;
#pragma unroll
        for (int ks = 0; ks < 2; ks++) {
            const int bb = (c * 2 + ks) * 256 + L;
            uint2 B[8];
#pragma unroll
            for (int ni = 0; ni < 8; ni++) B[ni] = sB[bb + ni * 32];
#pragma unroll
            for (int mi = 0; mi < 2; mi++) {
                const uint8_t* a = st + mi * 16 * SROWB;
                float2 d0 = *(const float2*)(a + off[ks][0]);
                float2 d1 = *(const float2*)(a + off[ks][1]);
                float2 d2 = *(const float2*)(a + off[ks][2]);
                float2 d3 = *(const float2*)(a + off[ks][3]);
                uint32_t ah[4], al[4];
                split2h(d0.x, d0.y, ah[0], al[0]);
                split2h(d1.x, d1.y, ah[1], al[1]);
                split2h(d2.x, d2.y, ah[2], al[2]);
                split2h(d3.x, d3.y, ah[3], al[3]);
#pragma unroll
                for (int ni = 0; ni < 8; ni++) {
                    mma16816(acc[mi][ni], ah, B[ni].x, B[ni].y);  // xh*wh
                    mma16816(acc[mi][ni], al, B[ni].x, B[ni].y);  // xl*wh
                }
            }
        }
        __syncwarp();   // stage s consumed by all lanes before reuse
    }

    // epilogue (proven mapping)
    const int kk2 = (L & 3) * 2;
#pragma unroll
    for (int mi = 0; mi < 2; mi++) {
        const size_t grow = row0 + wid * 32 + mi * 16 + (L >> 2);
#pragma unroll
        for (int ni = 0; ni < 8; ni++) {
            float* o0 = out + grow * 64 + ni * 8 + kk2;
            float* o1 = out + (grow + 8) * 64 + ni * 8 + kk2;
            *(float2*)o0 = make_float2(acc[mi][ni][0], acc[mi][ni][1]);
            *(float2*)o1 = make_float2(acc[mi][ni][2], acc[mi][ni][3]);
        }
    }
}

extern "C" void kernel_launch(void* const* d_in, const int* in_sizes, int n_in,
                              void* d_out, int out_size) {
    const float* xa = (const float*)d_in[0];
    const float* xb = (const float*)d_in[1];
    const float* wa = (const float*)d_in[2];
    const float* wb = (const float*)d_in[3];
    float* out = (float*)d_out;

    cudaFuncSetAttribute(sshe_mma_kernel,
                         cudaFuncAttributeMaxDynamicSharedMemorySize,
                         SMEM_BYTES);

    wconv_kernel<<<32, 256>>>(wa, wb);

    const int batch = in_sizes[0] / 256;     // 65536
    sshe_mma_kernel<<<batch / M_TILE, THREADS, SMEM_BYTES>>>(xa, xb, out);
}